// round 15
// baseline (speedup 1.0000x reference)
#include <cuda_runtime.h>
#include <cuda_fp16.h>
#include <cstdint>

// QConv1d via mma.sync f16 m16n8k16 implicit GEMM with cp.async double-buffered
// x tiles: gmem->smem fills run on the async copy engine (no register round
// trip, ~4 ops/thread/tile) fully overlapped with the previous tile's MMAs.
// x stays fp32 in smem; fp16 conversion happens in the fragment load
// (2x LDS.32 + 1 cvt per A reg, conflict-free with stride 268).
//
// out[n,o,l] = 0.125 * sum_{c,k} x[n,c,l+k-4] * w[o,c,k] + bias[o]
// GEMM: M = 256 l per tile, N = 64 (o), K = 576; k-step = 16 ch x 1 tap.
// B pre-packed in f16 fragment order once per persistent CTA.
// 512 threads = 16 warps, warp grid 8(M) x 2(N), 32x32 C per warp, 1 CTA/SM.

#define N_BATCH 8
#define C_IN    64
#define L_IN    16384
#define O_OUT   64
#define KSZ     9
#define PADK    4
#define SCALEF  0.125f

#define THREADS 512
#define TILE_L  256
#define TPERN   (L_IN / TILE_L)               // 64
#define NTILES  (N_BATCH * TPERN)             // 512
#define GRID    148

#define KTOT    (C_IN * KSZ)                  // 576
#define NSTEPS  36

#define XSF_STRIDE 268                        // fp32 per channel row; 268*2=536 = 24 mod 32
#define XSF_ROWB   (XSF_STRIDE * 4)           // 1072 bytes
#define XSF_FLOATS (C_IN * XSF_STRIDE)        // 17152
#define XSF_BYTES  (XSF_FLOATS * 4)           // 68608 per buffer

#define NQUADS     (C_IN * 66)                // 4224 uint4 per tile fill

// SMEM layout (bytes)
#define PK_BYTES   (NSTEPS * 256 * 8)         // 73728
#define SM_PK      0
#define SM_XS      PK_BYTES                   // double buffer
#define SM_BIAS    (SM_XS + 2 * XSF_BYTES)    // 210944
#define SM_TOTAL   (SM_BIAS + O_OUT * 4)      // 211200

__device__ __forceinline__ uint32_t smem_u32(const void* p) {
    uint32_t a;
    asm("{ .reg .u64 t; cvta.to.shared.u64 t, %1; cvt.u32.u64 %0, t; }" : "=r"(a) : "l"(p));
    return a;
}

__device__ __forceinline__ float lds_f32(uint32_t a) {
    float v;
    asm volatile("ld.shared.f32 %0, [%1];" : "=f"(v) : "r"(a));
    return v;
}

__device__ __forceinline__ void lds_v2(uint32_t a, uint32_t& v0, uint32_t& v1) {
    asm volatile("ld.shared.v2.b32 {%0, %1}, [%2];" : "=r"(v0), "=r"(v1) : "r"(a));
}

__device__ __forceinline__ uint32_t packh2(float a, float b) {
    __half2 h = __floats2half2_rn(a, b);      // low = a, high = b
    return *reinterpret_cast<uint32_t*>(&h);
}

__device__ __forceinline__ void mma_f16(float* c, const uint32_t* a, uint32_t b0, uint32_t b1) {
    asm volatile(
        "mma.sync.aligned.m16n8k16.row.col.f32.f16.f16.f32 "
        "{%0,%1,%2,%3}, {%4,%5,%6,%7}, {%8,%9}, {%0,%1,%2,%3};"
        : "+f"(c[0]), "+f"(c[1]), "+f"(c[2]), "+f"(c[3])
        : "r"(a[0]), "r"(a[1]), "r"(a[2]), "r"(a[3]), "r"(b0), "r"(b1));
}

__device__ __forceinline__ void cp_async16(uint32_t dst, const void* src, int sz) {
    asm volatile("cp.async.cg.shared.global [%0], [%1], 16, %2;"
                 :: "r"(dst), "l"(src), "r"(sz) : "memory");
}

// async fill of one fp32 x tile: 4224 uint4 via cp.async (zero-fill OOB quads)
__device__ __forceinline__ void fill_tile_async(uint32_t xsf, const float* xn,
                                                int tileL, int tid) {
    #pragma unroll
    for (int k = 0; k < 8; ++k) {
        int f  = tid + k * THREADS;
        int c  = f / 66;
        int q  = f - c * 66;
        int l0 = tileL - PADK + q * 4;
        bool ok = (l0 >= 0) && (l0 <= L_IN - 4);
        const float* src = xn + (size_t)c * L_IN + (ok ? l0 : 0);
        cp_async16(xsf + (uint32_t)(c * XSF_STRIDE + q * 4) * 4, src, ok ? 16 : 0);
    }
    if (tid < NQUADS - 8 * THREADS) {         // 128 leftover quads
        int f  = 8 * THREADS + tid;
        int c  = f / 66;
        int q  = f - c * 66;
        int l0 = tileL - PADK + q * 4;
        bool ok = (l0 >= 0) && (l0 <= L_IN - 4);
        const float* src = xn + (size_t)c * L_IN + (ok ? l0 : 0);
        cp_async16(xsf + (uint32_t)(c * XSF_STRIDE + q * 4) * 4, src, ok ? 16 : 0);
    }
}

__global__ void __launch_bounds__(THREADS, 1)
qconv1d_mma(const float* __restrict__ x, const float* __restrict__ w,
            const float* __restrict__ bias, float* __restrict__ out)
{
    extern __shared__ char smem[];
    float* bias_sm = (float*)(smem + SM_BIAS);

    const int tid  = threadIdx.x;
    const int wid  = tid >> 5;
    const int lane = tid & 31;
    const int mBlk = wid & 7;        // M block: rows [mBlk*32, +32) of 256
    const int nBlk = wid >> 3;       // N block: cols [nBlk*32, +32) of 64
    const int g    = lane >> 2;      // group id 0..7
    const int tig  = lane & 3;       // thread in group

    // ---- pack weights in f16 fragment order (once per persistent CTA) ----
    // uint2 index: s*256 + nB*128 + nt*32 + lane, s = a*4 + cg
    {
        uint2* pk = (uint2*)(smem + SM_PK);
        for (int i = tid; i < NSTEPS * 256; i += THREADS) {
            int li = i & 31;
            int nt = (i >> 5) & 3;
            int nB = (i >> 7) & 1;
            int s  = i >> 8;
            int a  = s >> 2;
            int cg = s & 3;
            int o  = nB * 32 + nt * 8 + (li >> 2);
            int c0 = cg * 16 + 2 * (li & 3);
            const float* wr = w + o * KTOT + a;
            uint2 v;
            v.x = packh2(wr[c0 * KSZ],       wr[(c0 + 1) * KSZ]);
            v.y = packh2(wr[(c0 + 8) * KSZ], wr[(c0 + 9) * KSZ]);
            pk[i] = v;
        }
        if (tid < O_OUT) bias_sm[tid] = bias[tid];
    }

    const uint32_t sbase = smem_u32(smem);
    // per-thread A base within a buffer: channel row 2*tig, m word (mBlk*32+g)
    const uint32_t xsOff = (uint32_t)(2 * tig) * XSF_ROWB + (uint32_t)(mBlk * 32 + g) * 4;
    const uint32_t pkB   = sbase + SM_PK + (uint32_t)(nBlk * 128 + lane) * 8;
    const uint32_t xsBuf[2] = { sbase + SM_XS, sbase + SM_XS + XSF_BYTES };

    // ---- prologue: async-fill buffer 0 with the first tile ----
    {
        const int t0 = blockIdx.x;            // < NTILES (148 <= 512)
        const float* xn = x + (size_t)(t0 / TPERN) * C_IN * L_IN;
        fill_tile_async(xsBuf[0], xn, (t0 % TPERN) * TILE_L, tid);
        asm volatile("cp.async.commit_group;" ::: "memory");
    }

    int buf = 0;
    for (int t = blockIdx.x; t < NTILES; t += GRID) {
        const int n     = t / TPERN;
        const int tileL = (t % TPERN) * TILE_L;

        // prefetch next tile into the other buffer (async), then wait for current
        const int tn = t + GRID;
        if (tn < NTILES) {
            const float* xnn = x + (size_t)(tn / TPERN) * C_IN * L_IN;
            fill_tile_async(xsBuf[buf ^ 1], xnn, (tn % TPERN) * TILE_L, tid);
            asm volatile("cp.async.commit_group;" ::: "memory");
            asm volatile("cp.async.wait_group 1;" ::: "memory");
        } else {
            asm volatile("cp.async.wait_group 0;" ::: "memory");
        }
        __syncthreads();    // current buffer (and pk on iter 0) visible to all

        const uint32_t xsA = xsBuf[buf] + xsOff;

        float acc[2][4][4];
        #pragma unroll
        for (int mt = 0; mt < 2; ++mt)
            #pragma unroll
            for (int nt = 0; nt < 4; ++nt)
                #pragma unroll
                for (int r = 0; r < 4; ++r) acc[mt][nt][r] = 0.0f;

        #pragma unroll 1
        for (int a = 0; a < KSZ; ++a) {            // tap
            const uint32_t pAa = xsA + (uint32_t)a * 4;
            const uint32_t pBa = pkB + (uint32_t)a * (4 * 2048);
            #pragma unroll
            for (int cg = 0; cg < 4; ++cg) {       // 16-channel group
                const uint32_t pA = pAa + (uint32_t)cg * (16 * XSF_ROWB);
                uint32_t af[2][4];
                #pragma unroll
                for (int mt = 0; mt < 2; ++mt) {
                    const uint32_t p = pA + mt * 64;
                    // fragment regs: (row g / g+8) x (channels c0,c0+1 / c0+8,c0+9)
                    float e0 = lds_f32(p);
                    float o0 = lds_f32(p + XSF_ROWB);
                    float e1 = lds_f32(p + 32);
                    float o1 = lds_f32(p + XSF_ROWB + 32);
                    float e2 = lds_f32(p + 8 * XSF_ROWB);
                    float o2 = lds_f32(p + 9 * XSF_ROWB);
                    float e3 = lds_f32(p + 8 * XSF_ROWB + 32);
                    float o3 = lds_f32(p + 9 * XSF_ROWB + 32);
                    af[mt][0] = packh2(e0, o0);
                    af[mt][1] = packh2(e1, o1);
                    af[mt][2] = packh2(e2, o2);
                    af[mt][3] = packh2(e3, o3);
                }
                uint32_t bf[4][2];
                #pragma unroll
                for (int nt = 0; nt < 4; ++nt)
                    lds_v2(pBa + cg * 2048 + nt * 256, bf[nt][0], bf[nt][1]);
                #pragma unroll
                for (int nt = 0; nt < 4; ++nt) {
                    mma_f16(acc[0][nt], af[0], bf[nt][0], bf[nt][1]);
                    mma_f16(acc[1][nt], af[1], bf[nt][0], bf[nt][1]);
                }
            }
        }
        __syncthreads();    // all warps done reading this buffer before it refills

        // ---- epilogue: scale + bias, direct stores ----
        float* ob = out + (size_t)n * O_OUT * L_IN + tileL;
        #pragma unroll
        for (int mt = 0; mt < 2; ++mt) {
            const int r0 = mBlk * 32 + mt * 16 + g;
            #pragma unroll
            for (int nt = 0; nt < 4; ++nt) {
                const int o0 = nBlk * 32 + nt * 8 + tig * 2;
                const float b0 = bias_sm[o0], b1 = bias_sm[o0 + 1];
                ob[(size_t)o0 * L_IN + r0]           = acc[mt][nt][0] * SCALEF + b0;
                ob[(size_t)(o0 + 1) * L_IN + r0]     = acc[mt][nt][1] * SCALEF + b1;
                ob[(size_t)o0 * L_IN + r0 + 8]       = acc[mt][nt][2] * SCALEF + b0;
                ob[(size_t)(o0 + 1) * L_IN + r0 + 8] = acc[mt][nt][3] * SCALEF + b1;
            }
        }

        buf ^= 1;
    }
}

extern "C" void kernel_launch(void* const* d_in, const int* in_sizes, int n_in,
                              void* d_out, int out_size)
{
    const float* x    = (const float*)d_in[0];
    const float* w    = (const float*)d_in[1];
    const float* bias = (const float*)d_in[2];
    float* out        = (float*)d_out;

    cudaFuncSetAttribute(qconv1d_mma,
                         cudaFuncAttributeMaxDynamicSharedMemorySize, SM_TOTAL);
    qconv1d_mma<<<GRID, THREADS, SM_TOTAL>>>(x, w, bias, out);
}